// round 6
// baseline (speedup 1.0000x reference)
#include <cuda_runtime.h>
#include <stdint.h>

#define BB 64
#define TT 256
#define NN 64
#define NPAIRS 2016               // 64*63/2 batch pairs
#define WG_PER_T 63               // 32-pair words per t
#define XPAD 68                   // padded row stride (floats) for xs
#define ROWB (XPAD * 4)           // 272 bytes per xs row

// g_H[0..4095]: Hamming accumulators (i<j). g_H[4096]: grid arrival counter.
__device__ int g_H[NN * NN + 1];

// ---------------- fully fused kernel: pack + Gram + barrier + distance ------
__global__ __launch_bounds__(512) void fusedKD(const float* __restrict__ in,
                                               float* __restrict__ out) {
    __shared__ __align__(16) float xs[BB][XPAD];          // 17.4 KB slab (reused as D)
    __shared__ __align__(16) uint32_t bits[WG_PER_T][NN]; // 16.1 KB bit matrix (reused as Hs)
    __shared__ uint32_t pr[NPAIRS];                       // 8.1 KB byte-offset pairs
    int tid = threadIdx.x;
    int t = blockIdx.x;

    // Load 64x64 slab (float4, coalesced) into padded smem rows.
    {
        const float4* src = (const float4*)in;
        for (int q = tid; q < BB * 16; q += 512) {
            int b = q >> 4, c = q & 15;
            *(float4*)&xs[b][c * 4] = src[(size_t)b * (TT * 16) + t * 16 + c];
        }
    }
    // Pair table: pr[p] = (a*272) | ((b*272) << 16), closed-form decode + fixup.
    for (int p = tid; p < NPAIRS; p += 512) {
        int a = (int)floorf(63.5f - sqrtf(4032.25f - 2.0f * (float)p));
        if (a < 0) a = 0; if (a > 62) a = 62;
        int cum = 63 * a - ((a * (a - 1)) >> 1);
        if (p < cum)               { a--; cum = 63 * a - ((a * (a - 1)) >> 1); }
        else if (p >= cum + 63 - a){ a++; cum = 63 * a - ((a * (a - 1)) >> 1); }
        int b = a + 1 + (p - cum);
        pr[p] = (uint32_t)(a * ROWB) | ((uint32_t)(b * ROWB) << 16);
    }
    __syncthreads();

    // Bit-pack: 63 wg x 8 col-groups (8 cols each) = 504 tasks, one per thread.
    if (tid < WG_PER_T * 8) {
        int wg = tid >> 3, cg = tid & 7;
        const uint32_t* prp = &pr[wg << 5];
        const char* xb = (const char*)xs + cg * 32;
        uint32_t w[8] = {0,0,0,0,0,0,0,0};
        #pragma unroll
        for (int s = 0; s < 32; s++) {
            uint32_t u = prp[s];
            const char* pa = xb + (u & 0xFFFFu);
            const char* pb = xb + (u >> 16);
            float4 fa0 = *(const float4*)pa;
            float4 fa1 = *(const float4*)(pa + 16);
            float4 fb0 = *(const float4*)pb;
            float4 fb1 = *(const float4*)(pb + 16);
            uint32_t m = 1u << s;
            w[0] |= (fa0.x > fb0.x) ? m : 0u;  w[1] |= (fa0.y > fb0.y) ? m : 0u;
            w[2] |= (fa0.z > fb0.z) ? m : 0u;  w[3] |= (fa0.w > fb0.w) ? m : 0u;
            w[4] |= (fa1.x > fb1.x) ? m : 0u;  w[5] |= (fa1.y > fb1.y) ? m : 0u;
            w[6] |= (fa1.z > fb1.z) ? m : 0u;  w[7] |= (fa1.w > fb1.w) ? m : 0u;
        }
        *(uint4*)&bits[wg][cg * 8]     = make_uint4(w[0], w[1], w[2], w[3]);
        *(uint4*)&bits[wg][cg * 8 + 4] = make_uint4(w[4], w[5], w[6], w[7]);
    }
    __syncthreads();

    // Gram: 136 upper-triangle 4x4 tiles, 16 accumulators, full 63-word sweep.
    if (tid < 136) {
        int ti = 0, rem = tid;
        while (rem >= 16 - ti) { rem -= 16 - ti; ti++; }
        int tj = ti + rem;
        int i0 = ti << 2, j0 = tj << 2;

        int acc[16];
        #pragma unroll
        for (int k = 0; k < 16; k++) acc[k] = 0;

        #pragma unroll 3
        for (int w = 0; w < WG_PER_T; w++) {
            uint4 bi = *(const uint4*)&bits[w][i0];
            uint4 bj = *(const uint4*)&bits[w][j0];
            uint32_t iv[4] = {bi.x, bi.y, bi.z, bi.w};
            uint32_t jv[4] = {bj.x, bj.y, bj.z, bj.w};
            #pragma unroll
            for (int ii = 0; ii < 4; ii++)
                #pragma unroll
                for (int jj = 0; jj < 4; jj++)
                    acc[ii * 4 + jj] += __popc(iv[ii] ^ jv[jj]);
        }
        #pragma unroll
        for (int k = 0; k < 16; k++) {
            int i = i0 + (k >> 2), j = j0 + (k & 3);
            if (i < j) atomicAdd(&g_H[i * NN + j], acc[k]);  // fire-and-forget RED
        }
    }
    __syncthreads();

    // ---- software grid barrier (all 256 CTAs are co-resident: single wave) ----
    if (tid == 0) {
        __threadfence();                       // make our REDs globally visible
        atomicAdd(&g_H[NN * NN], 1);           // arrive
        volatile int* cnt = &g_H[NN * NN];
        while (*cnt < TT) { }                  // wait for all arrivals
    }
    __syncthreads();

    // ---- epilogue: D = 1 - (1032192 - 4H)/2016, diag 0; each block writes 4 KB ----
    int*   Hs = (int*)bits;                    // reuse smem
    float* D  = (float*)xs;
    {
        const int4* src = (const int4*)g_H;
        int4* dst = (int4*)Hs;
        for (int k = tid; k < NN * NN / 4; k += 512) dst[k] = __ldcg(&src[k]);
    }
    __syncthreads();
    for (int k = tid; k < NN * NN; k += 512) {
        int i = k >> 6, j = k & 63;
        float d = 0.0f;
        if (i != j) {
            int h = (i < j) ? Hs[i * NN + j] : Hs[j * NN + i];
            float C = 1032192.0f - 4.0f * (float)h;   // 2K - 4H, K = 516096
            d = 1.0f - C * (1.0f / 2016.0f);
        }
        D[k] = d;
    }
    __syncthreads();
    {
        int cp = blockIdx.x >> 2;              // batch copy 0..63
        int q  = blockIdx.x & 3;               // quarter of the 16 KB matrix
        float4* o = (float4*)(out + (size_t)cp * (NN * NN)) + q * 256;
        const float4* s = (const float4*)D + q * 256;
        if (tid < 256) o[tid] = s[tid];
    }
}

extern "C" void kernel_launch(void* const* d_in, const int* in_sizes, int n_in,
                              void* d_out, int out_size) {
    (void)in_sizes; (void)n_in; (void)out_size;
    const float* in = (const float*)d_in[0];
    float* out = (float*)d_out;

    void* hptr = nullptr;
    cudaGetSymbolAddress(&hptr, g_H);
    cudaMemsetAsync(hptr, 0, (NN * NN + 1) * sizeof(int));  // H + arrival counter

    fusedKD<<<TT, 512>>>(in, out);
}

// round 7
// speedup vs baseline: 1.3174x; 1.3174x over previous
#include <cuda_runtime.h>
#include <stdint.h>

#define BB 64
#define TT 256
#define NN 64
#define BPAD 68                  // padded bits row stride (u32), 16B-aligned rows

__device__ int g_H[NN * NN];     // Hamming accumulators (only i<j used)

// ---------------- fused: shuffle bit-pack + XOR/popcount Gram, one block per t
// Word layout per column (64 words, identical mapping for every column):
//  word a      (a=0..31): bit w = [x[a] > x[32+w]]                  (1024 pairs)
//  word 32+a   (a=0..31): bit s-1  = [x[a] > x[(a+s)&31]], s=1..16  (lo half)
//                         bit 15+s = [x[32+a] > x[32+((a+s)&31)]]   (hi half)
//              lanes >= 16 mask bits 15,31 (s=16 duplicate pairs) -> 992 pairs
// Orientation varies per pair but is identical across columns, so XOR-popcount
// of word_i ^ word_j counts discordant pairs exactly; masked bits add 0.
__global__ __launch_bounds__(512) void fusedKD(const float4* __restrict__ in4) {
    __shared__ __align__(16) uint32_t bits[64][BPAD];  // 17.4 KB
    __shared__ __align__(16) int Hs[NN * NN];          // 16 KB block-local H
    const int tid  = threadIdx.x;
    const int t    = blockIdx.x;
    const int lane = tid & 31, warp = tid >> 5;

    // zero block-local H
    {
        int4* h4 = (int4*)Hs;
        for (int k = tid; k < 1024; k += 512) h4[k] = make_int4(0, 0, 0, 0);
    }

    // Each warp owns col-group cg = warp (cols 4cg..4cg+3).
    // Lane a loads x[a][t][cols], x[a+32][t][cols] (16KB slab -> L1 resident).
    float4 flo = __ldg(&in4[(size_t)lane * (TT * 16) + (size_t)t * 16 + warp]);
    float4 fhi = __ldg(&in4[(size_t)(lane + 32) * (TT * 16) + (size_t)t * 16 + warp]);
    float xl[4] = {flo.x, flo.y, flo.z, flo.w};
    float xh[4] = {fhi.x, fhi.y, fhi.z, fhi.w};

    #pragma unroll
    for (int k = 0; k < 4; k++) {
        uint32_t wA = 0u, wB = 0u;
        #pragma unroll
        for (int w = 0; w < 32; w++) {
            float xb = __shfl_sync(0xFFFFFFFFu, xh[k], w);     // broadcast x[32+w]
            if (xl[k] > xb) wA |= (1u << w);
        }
        #pragma unroll
        for (int s = 1; s <= 16; s++) {
            float rl = __shfl_sync(0xFFFFFFFFu, xl[k], lane + s);  // wraps mod 32
            float rh = __shfl_sync(0xFFFFFFFFu, xh[k], lane + s);
            if (xl[k] > rl) wB |= (1u << (s - 1));
            if (xh[k] > rh) wB |= (1u << (15 + s));
        }
        if (lane >= 16) wB &= 0x7FFF7FFFu;   // kill s=16 duplicate pairs
        int col = (warp << 2) + k;
        bits[lane][col]      = wA;
        bits[32 + lane][col] = wB;
    }
    __syncthreads();

    // Gram: 136 upper-tri 4x4 tiles x 4 chunks of 16 words = 544 tasks (all warps).
    for (int task = tid; task < 544; task += 512) {
        int tile = task >> 2, chunk = task & 3;
        int ti = 0, rem = tile;
        while (rem >= 16 - ti) { rem -= 16 - ti; ti++; }
        int tj = ti + rem;
        int i0 = ti << 2, j0 = tj << 2;
        int wb = chunk << 4;

        int acc[16];
        #pragma unroll
        for (int k = 0; k < 16; k++) acc[k] = 0;
        #pragma unroll
        for (int w = 0; w < 16; w++) {
            uint4 bi = *(const uint4*)&bits[wb + w][i0];
            uint4 bj = *(const uint4*)&bits[wb + w][j0];
            uint32_t iv[4] = {bi.x, bi.y, bi.z, bi.w};
            uint32_t jv[4] = {bj.x, bj.y, bj.z, bj.w};
            #pragma unroll
            for (int ii = 0; ii < 4; ii++)
                #pragma unroll
                for (int jj = 0; jj < 4; jj++)
                    acc[ii * 4 + jj] += __popc(iv[ii] ^ jv[jj]);
        }
        #pragma unroll
        for (int k = 0; k < 16; k++) {
            int i = i0 + (k >> 2), j = j0 + (k & 3);
            if (i < j) atomicAdd(&Hs[i * NN + j], acc[k]);   // smem ATOMS, spread
        }
    }
    __syncthreads();

    // One global RED per (i<j) cell: 2016 per block.
    #pragma unroll
    for (int r = 0; r < 8; r++) {
        int idx = (r << 9) + tid;
        int i = idx >> 6, j = idx & 63;
        int v = Hs[idx];
        if (i < j) atomicAdd(&g_H[idx], v);
    }
}

// ---------------- distance + broadcast: 256 blocks, one (copy, quarter) each --
// D[i,j] = 1 - (1032192 - 4H)/2016 (2K - 4H with K = 516096), diag 0.
__global__ __launch_bounds__(256) void phase3(float* __restrict__ out) {
    __shared__ __align__(16) int Hs[NN * NN];   // 16 KB
    int tid = threadIdx.x;
    int cp = blockIdx.x >> 2, q = blockIdx.x & 3;

    {
        const int4* s = (const int4*)g_H;
        int4* d = (int4*)Hs;
        for (int k = tid; k < 1024; k += 256) d[k] = __ldcg(&s[k]);
    }
    __syncthreads();

    int base = (q << 10) + (tid << 2);          // 4 contiguous cells, same row
    int i = base >> 6, j0 = base & 63;
    float v[4];
    #pragma unroll
    for (int u = 0; u < 4; u++) {
        int j = j0 + u;
        float d = 0.0f;
        if (i != j) {
            int h = (i < j) ? Hs[i * NN + j] : Hs[j * NN + i];
            d = 1.0f - (1032192.0f - 4.0f * (float)h) * (1.0f / 2016.0f);
        }
        v[u] = d;
    }
    *(float4*)(out + (size_t)cp * (NN * NN) + base) = make_float4(v[0], v[1], v[2], v[3]);
}

extern "C" void kernel_launch(void* const* d_in, const int* in_sizes, int n_in,
                              void* d_out, int out_size) {
    (void)in_sizes; (void)n_in; (void)out_size;
    const float4* in4 = (const float4*)d_in[0];
    float* out = (float*)d_out;

    void* hptr = nullptr;
    cudaGetSymbolAddress(&hptr, g_H);
    cudaMemsetAsync(hptr, 0, NN * NN * sizeof(int));

    fusedKD<<<TT, 512>>>(in4);
    phase3<<<TT, 256>>>(out);
}

// round 8
// speedup vs baseline: 1.4215x; 1.0790x over previous
#include <cuda_runtime.h>
#include <stdint.h>

#define BB 64
#define TT 256
#define NN 64
#define XPAD 68                  // padded xs row stride (floats)
#define BPAD 68                  // padded bits row stride (u32)
#define NTHR 544                 // 17 warps: 512 pack threads + exact Gram fit

__device__ int g_H[NN * NN];     // Hamming accumulators (only i<j used)

// ---------------- fused: shuffle bit-pack + XOR/popcount Gram, one block per t
// Word layout per column (64 words, identical mapping for every column):
//  word a      (a=0..31): bit w = [x[a] > x[32+w]]                  (1024 pairs)
//  word 32+a   (a=0..31): bit s-1  = [x[a] > x[(a+s)&31]], s=1..16  (lo half)
//                         bit 15+s = [x[32+a] > x[32+((a+s)&31)]]   (hi half)
//              lanes >= 16 mask bits 15,31 (s=16 duplicate pairs) -> 992 pairs
// Orientation varies per pair but is identical across columns, so XOR-popcount
// of word_i ^ word_j counts discordant pairs exactly; masked bits add 0.
__global__ __launch_bounds__(NTHR) void fusedKD(const float4* __restrict__ in4) {
    __shared__ __align__(16) float    xs[BB][XPAD];    // 17.4 KB staged slab
    __shared__ __align__(16) uint32_t bits[64][BPAD];  // 17.4 KB bit matrix
    __shared__ uint32_t lut[136];                      // tile -> (i0<<8)|j0
    const int tid  = threadIdx.x;
    const int t    = blockIdx.x;
    const int lane = tid & 31, warp = tid >> 5;

    // Coalesced staging of the 64x64 slab (1024 float4).
    for (int q = tid; q < BB * 16; q += NTHR) {
        int b = q >> 4, c = q & 15;
        *(float4*)&xs[b][c * 4] = in4[(size_t)b * (TT * 16) + (size_t)t * 16 + c];
    }
    // Tile LUT: 136 upper-triangle 4x4 tiles.
    if (tid < 136) {
        int ti = 0, rem = tid;
        while (rem >= 16 - ti) { rem -= 16 - ti; ti++; }
        int tj = ti + rem;
        lut[tid] = (uint32_t)((ti << 2) << 8) | (uint32_t)(tj << 2);
    }
    __syncthreads();

    // Shuffle bit-pack: warps 0..15, warp = col-group (4 cols), lane = batch a.
    if (tid < 512) {
        float4 flo = *(const float4*)&xs[lane][warp * 4];
        float4 fhi = *(const float4*)&xs[lane + 32][warp * 4];
        float xl[4] = {flo.x, flo.y, flo.z, flo.w};
        float xh[4] = {fhi.x, fhi.y, fhi.z, fhi.w};

        #pragma unroll
        for (int k = 0; k < 4; k++) {
            uint32_t wA = 0u, wB = 0u;
            #pragma unroll
            for (int w = 0; w < 32; w++) {
                float xb = __shfl_sync(0xFFFFFFFFu, xh[k], w);
                if (xl[k] > xb) wA |= (1u << w);
            }
            #pragma unroll
            for (int s = 1; s <= 16; s++) {
                float rl = __shfl_sync(0xFFFFFFFFu, xl[k], lane + s);  // mod 32
                float rh = __shfl_sync(0xFFFFFFFFu, xh[k], lane + s);
                if (xl[k] > rl) wB |= (1u << (s - 1));
                if (xh[k] > rh) wB |= (1u << (15 + s));
            }
            if (lane >= 16) wB &= 0x7FFF7FFFu;   // kill s=16 duplicate pairs
            int col = (warp << 2) + k;
            bits[lane][col]      = wA;
            bits[32 + lane][col] = wB;
        }
    }
    __syncthreads();

    // Gram: 136 tiles x 4 chunks(16 words) = 544 tasks, exactly one per thread.
    // The 4 chunk-threads of a tile are lanes {4m..4m+3} of one warp:
    // butterfly-reduce their partial acc, then one lane fires 16 global REDs.
    {
        uint32_t ij = lut[tid >> 2];
        int i0 = (int)(ij >> 8), j0 = (int)(ij & 255);
        int wb = (tid & 3) << 4;

        int acc[16];
        #pragma unroll
        for (int k = 0; k < 16; k++) acc[k] = 0;
        #pragma unroll
        for (int w = 0; w < 16; w++) {
            uint4 bi = *(const uint4*)&bits[wb + w][i0];
            uint4 bj = *(const uint4*)&bits[wb + w][j0];
            uint32_t iv[4] = {bi.x, bi.y, bi.z, bi.w};
            uint32_t jv[4] = {bj.x, bj.y, bj.z, bj.w};
            #pragma unroll
            for (int ii = 0; ii < 4; ii++)
                #pragma unroll
                for (int jj = 0; jj < 4; jj++)
                    acc[ii * 4 + jj] += __popc(iv[ii] ^ jv[jj]);
        }
        #pragma unroll
        for (int k = 0; k < 16; k++) {
            acc[k] += __shfl_xor_sync(0xFFFFFFFFu, acc[k], 1);
            acc[k] += __shfl_xor_sync(0xFFFFFFFFu, acc[k], 2);
        }
        if ((tid & 3) == 0) {
            #pragma unroll
            for (int k = 0; k < 16; k++) {
                int i = i0 + (k >> 2), j = j0 + (k & 3);
                if (i < j) atomicAdd(&g_H[i * NN + j], acc[k]);  // fire-and-forget
            }
        }
    }
}

// ---------------- distance + broadcast: 256 blocks, one (copy, quarter) each --
// D[i,j] = 1 - (1032192 - 4H)/2016 (2K - 4H with K = 516096), diag 0.
__global__ __launch_bounds__(256) void phase3(float* __restrict__ out) {
    __shared__ __align__(16) int Hs[NN * NN];   // 16 KB
    int tid = threadIdx.x;
    int cp = blockIdx.x >> 2, q = blockIdx.x & 3;

    {
        const int4* s = (const int4*)g_H;
        int4* d = (int4*)Hs;
        for (int k = tid; k < 1024; k += 256) d[k] = __ldg(&s[k]);
    }
    __syncthreads();

    int base = (q << 10) + (tid << 2);          // 4 contiguous cells, same row
    int i = base >> 6, j0 = base & 63;
    float v[4];
    #pragma unroll
    for (int u = 0; u < 4; u++) {
        int j = j0 + u;
        float d = 0.0f;
        if (i != j) {
            int h = (i < j) ? Hs[i * NN + j] : Hs[j * NN + i];
            d = 1.0f - (1032192.0f - 4.0f * (float)h) * (1.0f / 2016.0f);
        }
        v[u] = d;
    }
    *(float4*)(out + (size_t)cp * (NN * NN) + base) = make_float4(v[0], v[1], v[2], v[3]);
}

extern "C" void kernel_launch(void* const* d_in, const int* in_sizes, int n_in,
                              void* d_out, int out_size) {
    (void)in_sizes; (void)n_in; (void)out_size;
    const float4* in4 = (const float4*)d_in[0];
    float* out = (float*)d_out;

    void* hptr = nullptr;
    cudaGetSymbolAddress(&hptr, g_H);
    cudaMemsetAsync(hptr, 0, NN * NN * sizeof(int));

    fusedKD<<<TT, NTHR>>>(in4);
    phase3<<<TT, 256>>>(out);
}

// round 11
// speedup vs baseline: 1.5271x; 1.0743x over previous
#include <cuda_runtime.h>
#include <stdint.h>

#define BB 64
#define TT 256
#define NN 64
#define XPAD 68                  // padded xs row stride (floats)
#define BPAD 68                  // padded bits row stride (u32)
#define NTHR 544                 // 17 warps: 512 pack threads + exact Gram fit

__device__ int g_H[NN * NN];     // Hamming accumulators (only i<j used)

// ---------------- fused: shuffle bit-pack + XOR/popcount Gram, one block per t
// Word layout per column (64 words, identical mapping for every column):
//  word a      (a=0..31): bit w = [x[a] > x[32+w]]                  (1024 pairs)
//  word 32+a   (a=0..31): bit s-1  = [x[a] > x[(a+s)&31]], s=1..16  (lo half)
//                         bit 15+s = [x[32+a] > x[32+((a+s)&31)]]   (hi half)
//              lanes >= 16 mask bits 15,31 (s=16 duplicate pairs) -> 992 pairs
// Orientation varies per pair but is identical across columns, so XOR-popcount
// of word_i ^ word_j counts discordant pairs exactly; masked bits add 0.
__global__ __launch_bounds__(NTHR) void fusedKD(const float4* __restrict__ in4) {
    __shared__ __align__(16) float    xs[BB][XPAD];    // 17.4 KB staged slab
    __shared__ __align__(16) uint32_t bits[64][BPAD];  // 17.4 KB bit matrix
    __shared__ uint32_t lut[136];                      // tile -> (i0<<8)|j0
    const int tid  = threadIdx.x;
    const int t    = blockIdx.x;
    const int lane = tid & 31, warp = tid >> 5;

    // Coalesced staging of the 64x64 slab (1024 float4).
    for (int q = tid; q < BB * 16; q += NTHR) {
        int b = q >> 4, c = q & 15;
        *(float4*)&xs[b][c * 4] = in4[(size_t)b * (TT * 16) + (size_t)t * 16 + c];
    }
    // Tile LUT: 136 upper-triangle 4x4 tiles.
    if (tid < 136) {
        int ti = 0, rem = tid;
        while (rem >= 16 - ti) { rem -= 16 - ti; ti++; }
        int tj = ti + rem;
        lut[tid] = (uint32_t)((ti << 2) << 8) | (uint32_t)(tj << 2);
    }
    __syncthreads();

    // Shuffle bit-pack: warps 0..15, warp = col-group (4 cols), lane = batch a.
    if (tid < 512) {
        float4 flo = *(const float4*)&xs[lane][warp * 4];
        float4 fhi = *(const float4*)&xs[lane + 32][warp * 4];
        float xl[4] = {flo.x, flo.y, flo.z, flo.w};
        float xh[4] = {fhi.x, fhi.y, fhi.z, fhi.w};

        #pragma unroll
        for (int k = 0; k < 4; k++) {
            uint32_t wA = 0u, wB = 0u;
            #pragma unroll
            for (int w = 0; w < 32; w++) {
                float xb = __shfl_sync(0xFFFFFFFFu, xh[k], w);
                if (xl[k] > xb) wA |= (1u << w);
            }
            #pragma unroll
            for (int s = 1; s <= 16; s++) {
                float rl = __shfl_sync(0xFFFFFFFFu, xl[k], lane + s);  // mod 32
                float rh = __shfl_sync(0xFFFFFFFFu, xh[k], lane + s);
                if (xl[k] > rl) wB |= (1u << (s - 1));
                if (xh[k] > rh) wB |= (1u << (15 + s));
            }
            if (lane >= 16) wB &= 0x7FFF7FFFu;   // kill s=16 duplicate pairs
            int col = (warp << 2) + k;
            bits[lane][col]      = wA;
            bits[32 + lane][col] = wB;
        }
    }
    __syncthreads();

    // Gram: 136 tiles x 4 interleaved word-sets = 544 tasks, one per thread.
    // Thread r = tid&3 sweeps words r, r+4, ..., r+60: quad lanes read rows
    // w..w+3 (banks 4 apart, disjoint) and same-(row,col) loads across quads
    // are identical addresses (broadcast) -> conflict-free crossbar traffic.
    {
        uint32_t ij = lut[tid >> 2];
        int i0 = (int)(ij >> 8), j0 = (int)(ij & 255);
        int r = tid & 3;

        int acc[16];
        #pragma unroll
        for (int k = 0; k < 16; k++) acc[k] = 0;
        #pragma unroll
        for (int step = 0; step < 16; step++) {
            int w = r + (step << 2);
            uint4 bi = *(const uint4*)&bits[w][i0];
            uint4 bj = *(const uint4*)&bits[w][j0];
            uint32_t iv[4] = {bi.x, bi.y, bi.z, bi.w};
            uint32_t jv[4] = {bj.x, bj.y, bj.z, bj.w};
            #pragma unroll
            for (int ii = 0; ii < 4; ii++)
                #pragma unroll
                for (int jj = 0; jj < 4; jj++)
                    acc[ii * 4 + jj] += __popc(iv[ii] ^ jv[jj]);
        }
        #pragma unroll
        for (int k = 0; k < 16; k++) {
            acc[k] += __shfl_xor_sync(0xFFFFFFFFu, acc[k], 1);
            acc[k] += __shfl_xor_sync(0xFFFFFFFFu, acc[k], 2);
        }
        if (r == 0) {
            #pragma unroll
            for (int k = 0; k < 16; k++) {
                int i = i0 + (k >> 2), j = j0 + (k & 3);
                if (i < j) atomicAdd(&g_H[i * NN + j], acc[k]);  // fire-and-forget
            }
        }
    }
}

// ---------------- distance + broadcast: 256 blocks, one (copy, quarter) each --
// D[i,j] = 1 - (1032192 - 4H)/2016 (2K - 4H with K = 516096), diag 0.
__global__ __launch_bounds__(256) void phase3(float* __restrict__ out) {
    __shared__ __align__(16) int Hs[NN * NN];   // 16 KB
    int tid = threadIdx.x;
    int cp = blockIdx.x >> 2, q = blockIdx.x & 3;

    {
        const int4* s = (const int4*)g_H;
        int4* d = (int4*)Hs;
        for (int k = tid; k < 1024; k += 256) d[k] = __ldg(&s[k]);
    }
    __syncthreads();

    int base = (q << 10) + (tid << 2);          // 4 contiguous cells, same row
    int i = base >> 6, j0 = base & 63;
    float v[4];
    #pragma unroll
    for (int u = 0; u < 4; u++) {
        int j = j0 + u;
        float d = 0.0f;
        if (i != j) {
            int h = (i < j) ? Hs[i * NN + j] : Hs[j * NN + i];
            d = 1.0f - (1032192.0f - 4.0f * (float)h) * (1.0f / 2016.0f);
        }
        v[u] = d;
    }
    *(float4*)(out + (size_t)cp * (NN * NN) + base) = make_float4(v[0], v[1], v[2], v[3]);
}

extern "C" void kernel_launch(void* const* d_in, const int* in_sizes, int n_in,
                              void* d_out, int out_size) {
    (void)in_sizes; (void)n_in; (void)out_size;
    const float4* in4 = (const float4*)d_in[0];
    float* out = (float*)d_out;

    void* hptr = nullptr;
    cudaGetSymbolAddress(&hptr, g_H);
    cudaMemsetAsync(hptr, 0, NN * NN * sizeof(int));

    fusedKD<<<TT, NTHR>>>(in4);
    phase3<<<TT, 256>>>(out);
}